// round 1
// baseline (speedup 1.0000x reference)
#include <cuda_runtime.h>
#include <cstdint>
#include <cstddef>
#include <math.h>

#define NB  16
#define NLQ 1024
#define NLK 1024
#define NDK 256
#define NDV 256

// ---------------- scratch (device globals: allocation-free) ----------------
__device__ float    g_ks[NB * NLK];
__device__ float    g_blkmax[NB * NLK / 8];
__device__ float    g_maxf[NB];
__device__ float    g_e[NB * NLK];
__device__ unsigned g_vp[(size_t)NB * NLK * NDV];   // tf32-rounded e*V, 16 MB

// ---------------- kernel 1: k_s[b,k] = key[b,k,:]·w, per-block max ----------
__global__ void ks_kernel(const float* __restrict__ key, const float* __restrict__ w) {
    __shared__ float ws[NDK];
    __shared__ float bm[8];
    int t = threadIdx.x;              // 256 threads
    ws[t] = w[t];
    __syncthreads();
    int warp = t >> 5, lane = t & 31;
    int row = blockIdx.x * 8 + warp;  // global (b*LK + k)
    const float* kp = key + (size_t)row * NDK;
    float s = 0.f;
#pragma unroll
    for (int i = 0; i < 8; i++) s = fmaf(kp[lane + 32 * i], ws[lane + 32 * i], s);
#pragma unroll
    for (int o = 16; o; o >>= 1) s += __shfl_xor_sync(0xffffffffu, s, o);
    if (lane == 0) { g_ks[row] = s; bm[warp] = s; }
    __syncthreads();
    if (t == 0) {
        float m = bm[0];
#pragma unroll
        for (int i = 1; i < 8; i++) m = fmaxf(m, bm[i]);
        g_blkmax[blockIdx.x] = m;
    }
}

// ---------------- kernel 2: per-batch max reduction -------------------------
__global__ void maxred_kernel() {
    __shared__ float s[128];
    int b = blockIdx.x, t = threadIdx.x;  // 16 blocks x 128 threads
    s[t] = g_blkmax[b * 128 + t];
    __syncthreads();
    for (int o = 64; o; o >>= 1) {
        if (t < o) s[t] = fmaxf(s[t], s[t + o]);
        __syncthreads();
    }
    if (t == 0) g_maxf[b] = s[0];
}

// ---------------- kernel 3: e[b,k], V'[b,k,v] = tf32(e * value) -------------
__global__ void vp_kernel(const float* __restrict__ value) {
    int row = blockIdx.x;          // B*LK rows
    int t = threadIdx.x;           // 256 threads = DV
    int b = row >> 10;
    float e = expf(g_ks[row] - g_maxf[b]);
    float v = value[(size_t)row * NDV + t];
    float p = e * v;
    unsigned o;
    asm("cvt.rna.tf32.f32 %0, %1;" : "=r"(o) : "f"(p));
    g_vp[(size_t)row * NDV + t] = o;
    if (t == 0) g_e[row] = e;
}

// ---------------- kernel 4: num = mask @ V', den folded in, out = num/den ---
#define BM 128
#define BN 256
#define BK 32
#define APITCH 40     // k-permuted A rows, padded (conflict-free lds.64)
#define BPITCH 264    // B rows padded (conflict-free broadcast lds.32)
#define AS_BUF (BM * APITCH)   // 5120 floats
#define BS_BUF (BK * BPITCH)   // 8448 floats
#define SMEM_FLOATS (2 * AS_BUF + 2 * BS_BUF + 64 + 128)
#define SMEM_BYTES (SMEM_FLOATS * 4)

__global__ __launch_bounds__(512, 1)
void attn_gemm_kernel(const int* __restrict__ mask, float* __restrict__ out) {
    extern __shared__ float sm[];
    float* As   = sm;
    float* Bs   = sm + 2 * AS_BUF;
    float* Es   = sm + 2 * AS_BUF + 2 * BS_BUF;   // e chunks, 2 x 32
    float* Dens = Es + 64;                        // 128 row denominators

    const int b     = blockIdx.y;
    const int qbase = blockIdx.x * BM;
    const int tid   = threadIdx.x;
    const int lane  = tid & 31;
    const int wid   = tid >> 5;
    const int warpM = wid >> 3;   // 0..1
    const int warpN = wid & 7;    // 0..7
    const int g     = lane >> 2;  // mma group 0..7
    const int th    = lane & 3;   // mma thread-in-group

    const int* mrow = mask + (size_t)(b * NLQ + qbase + (tid >> 2)) * NLK;
    const int mg = tid & 3;
    const unsigned* vpb = g_vp + (size_t)b * NLK * NDV;
    const float* eb = g_e + b * NLK;

    float c[4][4][4];
#pragma unroll
    for (int i = 0; i < 4; i++)
#pragma unroll
        for (int j = 0; j < 4; j++)
#pragma unroll
            for (int k = 0; k < 4; k++) c[i][j][k] = 0.f;
    float dacc[4][2] = {{0.f, 0.f}, {0.f, 0.f}, {0.f, 0.f}, {0.f, 0.f}};

    int4 pa0, pa1;
    float pe = 0.f;
    // permuted k positions: original kk -> k' = (k>>3)*8 + 2*(kk&3) + (kk>>2)
    const int gg1 = mg + 4;
    const int sts_base0 = ((mg >> 1) << 3) | (mg & 1);
    const int sts_base1 = ((gg1 >> 1) << 3) | (gg1 & 1);

    unsigned bs_addr = (unsigned)__cvta_generic_to_shared(Bs);

    auto load_glb = [&](int ko, int nb_) {
        pa0 = *(const int4*)(mrow + ko + mg * 4);
        pa1 = *(const int4*)(mrow + ko + (mg + 4) * 4);
        if (tid < 32) pe = eb[ko + tid];
        unsigned bdst = bs_addr + (unsigned)(nb_ * BS_BUF * 4);
#pragma unroll
        for (int j = 0; j < 4; j++) {
            int id = tid + 512 * j;
            int kr = id >> 6, c4 = id & 63;
            const unsigned* src = vpb + (size_t)(ko + kr) * NDV + c4 * 4;
            asm volatile("cp.async.cg.shared.global [%0], [%1], 16;\n"
                         :: "r"(bdst + (unsigned)(kr * BPITCH * 4 + c4 * 16)), "l"(src));
        }
        asm volatile("cp.async.commit_group;\n" ::: "memory");
    };

    auto sts_a = [&](int nb_) {
        float* Ar = As + nb_ * AS_BUF + (tid >> 2) * APITCH;
        Ar[sts_base0 + 0] = (float)pa0.x; Ar[sts_base0 + 2] = (float)pa0.y;
        Ar[sts_base0 + 4] = (float)pa0.z; Ar[sts_base0 + 6] = (float)pa0.w;
        Ar[sts_base1 + 0] = (float)pa1.x; Ar[sts_base1 + 2] = (float)pa1.y;
        Ar[sts_base1 + 4] = (float)pa1.z; Ar[sts_base1 + 6] = (float)pa1.w;
        if (tid < 32) Es[nb_ * 32 + tid] = pe;
    };

    auto compute = [&](int buf) {
        const float* A  = As + buf * AS_BUF;
        const float* Bm = Bs + buf * BS_BUF;
        const float* E  = Es + buf * 32;
#pragma unroll
        for (int ks = 0; ks < 4; ks++) {
            float a[4][4];
            const int kp = ks * 8 + 2 * th;
#pragma unroll
            for (int mt = 0; mt < 4; mt++) {
                const int r0 = warpM * 64 + mt * 16 + g;
                float2 p0 = *(const float2*)(A + r0 * APITCH + kp);
                float2 p1 = *(const float2*)(A + (r0 + 8) * APITCH + kp);
                a[mt][0] = p0.x; a[mt][2] = p0.y;   // k = ks*8+th, ks*8+th+4
                a[mt][1] = p1.x; a[mt][3] = p1.y;
            }
            float bb[4][2];
            const int kr = ks * 8 + th;
#pragma unroll
            for (int nt = 0; nt < 4; nt++) {
                const int col = warpN * 32 + nt * 8 + g;
                bb[nt][0] = Bm[kr * BPITCH + col];
                bb[nt][1] = Bm[(kr + 4) * BPITCH + col];
            }
            if (warpN == 0) {   // fp32 denominator from the same A fragments
                float e0 = E[ks * 8 + th], e1 = E[ks * 8 + th + 4];
#pragma unroll
                for (int mt = 0; mt < 4; mt++) {
                    dacc[mt][0] = fmaf(a[mt][0], e0, fmaf(a[mt][2], e1, dacc[mt][0]));
                    dacc[mt][1] = fmaf(a[mt][1], e0, fmaf(a[mt][3], e1, dacc[mt][1]));
                }
            }
#pragma unroll
            for (int mt = 0; mt < 4; mt++)
#pragma unroll
                for (int nt = 0; nt < 4; nt++)
                    asm volatile(
                        "mma.sync.aligned.m16n8k8.row.col.f32.tf32.tf32.f32 "
                        "{%0,%1,%2,%3}, {%4,%5,%6,%7}, {%8,%9}, {%0,%1,%2,%3};\n"
                        : "+f"(c[mt][nt][0]), "+f"(c[mt][nt][1]),
                          "+f"(c[mt][nt][2]), "+f"(c[mt][nt][3])
                        : "r"(__float_as_uint(a[mt][0])), "r"(__float_as_uint(a[mt][1])),
                          "r"(__float_as_uint(a[mt][2])), "r"(__float_as_uint(a[mt][3])),
                          "r"(__float_as_uint(bb[nt][0])), "r"(__float_as_uint(bb[nt][1])));
        }
    };

    // ---- 2-stage pipeline ----
    load_glb(0, 0);
    sts_a(0);
    const int NK = NLK / BK;   // 32
    for (int it = 0; it < NK; ++it) {
        int cb = it & 1, nb_ = cb ^ 1;
        asm volatile("cp.async.wait_group 0;\n" ::: "memory");
        __syncthreads();
        if (it + 1 < NK) load_glb((it + 1) * BK, nb_);
        compute(cb);
        if (it + 1 < NK) sts_a(nb_);
    }

    // ---- denominator reduce (warpN==0 warps own it) ----
    if (warpN == 0) {
#pragma unroll
        for (int mt = 0; mt < 4; mt++)
#pragma unroll
            for (int j = 0; j < 2; j++) {
                float v = dacc[mt][j];
                v += __shfl_xor_sync(0xffffffffu, v, 1);
                v += __shfl_xor_sync(0xffffffffu, v, 2);
                if (th == 0) Dens[warpM * 64 + mt * 16 + g + 8 * j] = v;
            }
    }
    __syncthreads();

    // ---- epilogue: out = num / den ----
#pragma unroll
    for (int mt = 0; mt < 4; mt++) {
        const int r0 = warpM * 64 + mt * 16 + g;
        float i0 = 1.0f / Dens[r0];
        float i1 = 1.0f / Dens[r0 + 8];
#pragma unroll
        for (int nt = 0; nt < 4; nt++) {
            const int col = warpN * 32 + nt * 8 + 2 * th;
            float2 o0 = make_float2(c[mt][nt][0] * i0, c[mt][nt][1] * i0);
            float2 o1 = make_float2(c[mt][nt][2] * i1, c[mt][nt][3] * i1);
            *(float2*)(out + (size_t)(b * NLQ + qbase + r0) * NDV + col) = o0;
            *(float2*)(out + (size_t)(b * NLQ + qbase + r0 + 8) * NDV + col) = o1;
        }
    }
}

// ---------------- launcher --------------------------------------------------
extern "C" void kernel_launch(void* const* d_in, const int* in_sizes, int n_in,
                              void* d_out, int out_size) {
    // metadata order: query, key, value, w, mask  (query is provably unused)
    const float* key   = (const float*)d_in[1];
    const float* value = (const float*)d_in[2];
    const float* w     = (const float*)d_in[3];
    const int*   mask  = (const int*)d_in[4];
    float*       out   = (float*)d_out;

    cudaFuncSetAttribute(attn_gemm_kernel,
                         cudaFuncAttributeMaxDynamicSharedMemorySize, SMEM_BYTES);

    ks_kernel<<<NB * NLK / 8, 256>>>(key, w);
    maxred_kernel<<<NB, 128>>>();
    vp_kernel<<<NB * NLK, 256>>>(value);
    dim3 grid(NLQ / BM, NB);
    attn_gemm_kernel<<<grid, 512, SMEM_BYTES>>>(mask, out);
}

// round 2
// speedup vs baseline: 1.0028x; 1.0028x over previous
#include <cuda_runtime.h>
#include <cstdint>
#include <cstddef>
#include <math.h>

#define NB  16
#define NLQ 1024
#define NLK 1024
#define NDK 256
#define NDV 256

// ---------------- scratch (device globals: allocation-free) ----------------
__device__ float    g_ks[NB * NLK];
__device__ float    g_blkmax[NB * NLK / 8];
__device__ float    g_maxf[NB];
__device__ float    g_e[NB * NLK];
__device__ unsigned g_vp[(size_t)NB * NLK * NDV];   // tf32-rounded e*V, 16 MB

// ---------------- kernel 1: k_s[b,k] = key[b,k,:]·w, per-block max ----------
__global__ void ks_kernel(const float* __restrict__ key, const float* __restrict__ w) {
    __shared__ float ws[NDK];
    __shared__ float bm[8];
    int t = threadIdx.x;              // 256 threads
    ws[t] = w[t];
    __syncthreads();
    int warp = t >> 5, lane = t & 31;
    int row = blockIdx.x * 8 + warp;  // global (b*LK + k)
    const float* kp = key + (size_t)row * NDK;
    float s = 0.f;
#pragma unroll
    for (int i = 0; i < 8; i++) s = fmaf(kp[lane + 32 * i], ws[lane + 32 * i], s);
#pragma unroll
    for (int o = 16; o; o >>= 1) s += __shfl_xor_sync(0xffffffffu, s, o);
    if (lane == 0) { g_ks[row] = s; bm[warp] = s; }
    __syncthreads();
    if (t == 0) {
        float m = bm[0];
#pragma unroll
        for (int i = 1; i < 8; i++) m = fmaxf(m, bm[i]);
        g_blkmax[blockIdx.x] = m;
    }
}

// ---------------- kernel 2: per-batch max reduction -------------------------
__global__ void maxred_kernel() {
    __shared__ float s[128];
    int b = blockIdx.x, t = threadIdx.x;  // 16 blocks x 128 threads
    s[t] = g_blkmax[b * 128 + t];
    __syncthreads();
    for (int o = 64; o; o >>= 1) {
        if (t < o) s[t] = fmaxf(s[t], s[t + o]);
        __syncthreads();
    }
    if (t == 0) g_maxf[b] = s[0];
}

// ---------------- kernel 3: e[b,k], V'[b,k,v] = tf32(e * value) -------------
__global__ void vp_kernel(const float* __restrict__ value) {
    int row = blockIdx.x;          // B*LK rows
    int t = threadIdx.x;           // 256 threads = DV
    int b = row >> 10;
    float e = expf(g_ks[row] - g_maxf[b]);
    float v = value[(size_t)row * NDV + t];
    float p = e * v;
    unsigned o;
    asm("cvt.rna.tf32.f32 %0, %1;" : "=r"(o) : "f"(p));
    g_vp[(size_t)row * NDV + t] = o;
    if (t == 0) g_e[row] = e;
}

// ---------------- kernel 4: num = mask @ V', den folded in, out = num/den ---
#define BM 128
#define BN 256
#define BK 32
#define APITCH 40     // k-permuted A rows, padded (conflict-free lds.64)
#define BPITCH 264    // B rows padded (conflict-free broadcast lds.32)
#define AS_BUF (BM * APITCH)   // 5120 floats
#define BS_BUF (BK * BPITCH)   // 8448 floats
#define SMEM_FLOATS (2 * AS_BUF + 2 * BS_BUF + 64 + 128)
#define SMEM_BYTES (SMEM_FLOATS * 4)

__global__ __launch_bounds__(512, 1)
void attn_gemm_kernel(const int* __restrict__ mask, float* __restrict__ out) {
    extern __shared__ float sm[];
    float* As   = sm;
    float* Bs   = sm + 2 * AS_BUF;
    float* Es   = sm + 2 * AS_BUF + 2 * BS_BUF;   // e chunks, 2 x 32
    float* Dens = Es + 64;                        // 128 row denominators

    const int b     = blockIdx.y;
    const int qbase = blockIdx.x * BM;
    const int tid   = threadIdx.x;
    const int lane  = tid & 31;
    const int wid   = tid >> 5;
    const int warpM = wid >> 3;   // 0..1
    const int warpN = wid & 7;    // 0..7
    const int g     = lane >> 2;  // mma group 0..7
    const int th    = lane & 3;   // mma thread-in-group

    const int* mrow = mask + (size_t)(b * NLQ + qbase + (tid >> 2)) * NLK;
    const int mg = tid & 3;
    const unsigned* vpb = g_vp + (size_t)b * NLK * NDV;
    const float* eb = g_e + b * NLK;

    float c[4][4][4];
#pragma unroll
    for (int i = 0; i < 4; i++)
#pragma unroll
        for (int j = 0; j < 4; j++)
#pragma unroll
            for (int k = 0; k < 4; k++) c[i][j][k] = 0.f;
    float dacc[4][2] = {{0.f, 0.f}, {0.f, 0.f}, {0.f, 0.f}, {0.f, 0.f}};

    int4 pa0, pa1;
    float pe = 0.f;
    // permuted k positions: original kk -> k' = (k>>3)*8 + 2*(kk&3) + (kk>>2)
    const int gg1 = mg + 4;
    const int sts_base0 = ((mg >> 1) << 3) | (mg & 1);
    const int sts_base1 = ((gg1 >> 1) << 3) | (gg1 & 1);

    unsigned bs_addr = (unsigned)__cvta_generic_to_shared(Bs);

    auto load_glb = [&](int ko, int nb_) {
        pa0 = *(const int4*)(mrow + ko + mg * 4);
        pa1 = *(const int4*)(mrow + ko + (mg + 4) * 4);
        if (tid < 32) pe = eb[ko + tid];
        unsigned bdst = bs_addr + (unsigned)(nb_ * BS_BUF * 4);
#pragma unroll
        for (int j = 0; j < 4; j++) {
            int id = tid + 512 * j;
            int kr = id >> 6, c4 = id & 63;
            const unsigned* src = vpb + (size_t)(ko + kr) * NDV + c4 * 4;
            asm volatile("cp.async.cg.shared.global [%0], [%1], 16;\n"
                         :: "r"(bdst + (unsigned)(kr * BPITCH * 4 + c4 * 16)), "l"(src));
        }
        asm volatile("cp.async.commit_group;\n" ::: "memory");
    };

    auto sts_a = [&](int nb_) {
        float* Ar = As + nb_ * AS_BUF + (tid >> 2) * APITCH;
        Ar[sts_base0 + 0] = (float)pa0.x; Ar[sts_base0 + 2] = (float)pa0.y;
        Ar[sts_base0 + 4] = (float)pa0.z; Ar[sts_base0 + 6] = (float)pa0.w;
        Ar[sts_base1 + 0] = (float)pa1.x; Ar[sts_base1 + 2] = (float)pa1.y;
        Ar[sts_base1 + 4] = (float)pa1.z; Ar[sts_base1 + 6] = (float)pa1.w;
        if (tid < 32) Es[nb_ * 32 + tid] = pe;
    };

    auto compute = [&](int buf) {
        const float* A  = As + buf * AS_BUF;
        const float* Bm = Bs + buf * BS_BUF;
        const float* E  = Es + buf * 32;
#pragma unroll
        for (int ks = 0; ks < 4; ks++) {
            float a[4][4];
            const int kp = ks * 8 + 2 * th;
#pragma unroll
            for (int mt = 0; mt < 4; mt++) {
                const int r0 = warpM * 64 + mt * 16 + g;
                float2 p0 = *(const float2*)(A + r0 * APITCH + kp);
                float2 p1 = *(const float2*)(A + (r0 + 8) * APITCH + kp);
                a[mt][0] = p0.x; a[mt][2] = p0.y;   // k = ks*8+th, ks*8+th+4
                a[mt][1] = p1.x; a[mt][3] = p1.y;
            }
            float bb[4][2];
            const int kr = ks * 8 + th;
#pragma unroll
            for (int nt = 0; nt < 4; nt++) {
                const int col = warpN * 32 + nt * 8 + g;
                bb[nt][0] = Bm[kr * BPITCH + col];
                bb[nt][1] = Bm[(kr + 4) * BPITCH + col];
            }
            if (warpN == 0) {   // fp32 denominator from the same A fragments
                float e0 = E[ks * 8 + th], e1 = E[ks * 8 + th + 4];
#pragma unroll
                for (int mt = 0; mt < 4; mt++) {
                    dacc[mt][0] = fmaf(a[mt][0], e0, fmaf(a[mt][2], e1, dacc[mt][0]));
                    dacc[mt][1] = fmaf(a[mt][1], e0, fmaf(a[mt][3], e1, dacc[mt][1]));
                }
            }
#pragma unroll
            for (int mt = 0; mt < 4; mt++)
#pragma unroll
                for (int nt = 0; nt < 4; nt++)
                    asm volatile(
                        "mma.sync.aligned.m16n8k8.row.col.f32.tf32.tf32.f32 "
                        "{%0,%1,%2,%3}, {%4,%5,%6,%7}, {%8,%9}, {%0,%1,%2,%3};\n"
                        : "+f"(c[mt][nt][0]), "+f"(c[mt][nt][1]),
                          "+f"(c[mt][nt][2]), "+f"(c[mt][nt][3])
                        : "r"(__float_as_uint(a[mt][0])), "r"(__float_as_uint(a[mt][1])),
                          "r"(__float_as_uint(a[mt][2])), "r"(__float_as_uint(a[mt][3])),
                          "r"(__float_as_uint(bb[nt][0])), "r"(__float_as_uint(bb[nt][1])));
        }
    };

    // ---- 2-stage pipeline ----
    load_glb(0, 0);
    sts_a(0);
    const int NK = NLK / BK;   // 32
    for (int it = 0; it < NK; ++it) {
        int cb = it & 1, nb_ = cb ^ 1;
        asm volatile("cp.async.wait_group 0;\n" ::: "memory");
        __syncthreads();
        if (it + 1 < NK) load_glb((it + 1) * BK, nb_);
        compute(cb);
        if (it + 1 < NK) sts_a(nb_);
    }

    // ---- denominator reduce (warpN==0 warps own it) ----
    if (warpN == 0) {
#pragma unroll
        for (int mt = 0; mt < 4; mt++)
#pragma unroll
            for (int j = 0; j < 2; j++) {
                float v = dacc[mt][j];
                v += __shfl_xor_sync(0xffffffffu, v, 1);
                v += __shfl_xor_sync(0xffffffffu, v, 2);
                if (th == 0) Dens[warpM * 64 + mt * 16 + g + 8 * j] = v;
            }
    }
    __syncthreads();

    // ---- epilogue: out = num / den ----
#pragma unroll
    for (int mt = 0; mt < 4; mt++) {
        const int r0 = warpM * 64 + mt * 16 + g;
        float i0 = 1.0f / Dens[r0];
        float i1 = 1.0f / Dens[r0 + 8];
#pragma unroll
        for (int nt = 0; nt < 4; nt++) {
            const int col = warpN * 32 + nt * 8 + 2 * th;
            float2 o0 = make_float2(c[mt][nt][0] * i0, c[mt][nt][1] * i0);
            float2 o1 = make_float2(c[mt][nt][2] * i1, c[mt][nt][3] * i1);
            *(float2*)(out + (size_t)(b * NLQ + qbase + r0) * NDV + col) = o0;
            *(float2*)(out + (size_t)(b * NLQ + qbase + r0 + 8) * NDV + col) = o1;
        }
    }
}

// ---------------- launcher --------------------------------------------------
extern "C" void kernel_launch(void* const* d_in, const int* in_sizes, int n_in,
                              void* d_out, int out_size) {
    // metadata order: query, key, value, w, mask  (query is provably unused)
    const float* key   = (const float*)d_in[1];
    const float* value = (const float*)d_in[2];
    const float* w     = (const float*)d_in[3];
    const int*   mask  = (const int*)d_in[4];
    float*       out   = (float*)d_out;

    cudaFuncSetAttribute(attn_gemm_kernel,
                         cudaFuncAttributeMaxDynamicSharedMemorySize, SMEM_BYTES);

    ks_kernel<<<NB * NLK / 8, 256>>>(key, w);
    maxred_kernel<<<NB, 128>>>();
    vp_kernel<<<NB * NLK, 256>>>(value);
    dim3 grid(NLQ / BM, NB);
    attn_gemm_kernel<<<grid, 512, SMEM_BYTES>>>(mask, out);
}